// round 1
// baseline (speedup 1.0000x reference)
#include <cuda_runtime.h>
#include <math.h>

#define B_    8
#define N_    8192
#define C_    91
#define CM_   90
#define K_    1000
#define MAXT_ 100
#define NPROB (B_*CM_)

#define BBOX_CLIP 4.135166556742356f
#define IOU_THR   0.3f

// ---------------- scratch (device globals: allocation-free) ----------------
__device__ float g_scores[B_*CM_*N_];        // [b][cm][n]  transposed scores
__device__ float g_topk_score[NPROB*K_];     // per (b,cm) sorted top-1000 scores
__device__ int   g_topk_idx[NPROB*K_];       // original proposal index
__device__ float g_nboxes[NPROB*K_*4];       // decoded, clipped, normalized boxes
__device__ float g_kept[NPROB*K_];           // kept score or -1.0

// ---------------- K1: softmax + transpose ----------------
__global__ void softmax_kernel(const float* __restrict__ cls)
{
    __shared__ float tile[C_][33];            // [class][row-in-tile]
    int cta  = blockIdx.x;
    int b    = cta / (N_/32);
    int n0   = (cta % (N_/32)) * 32;
    int warp = threadIdx.x >> 5;
    int lane = threadIdx.x & 31;

    for (int rr = 0; rr < 4; rr++) {
        int r = warp*4 + rr;
        const float* row = cls + ((size_t)b*N_ + n0 + r) * C_;
        float v0 = row[lane];
        float v1 = row[lane + 32];
        bool  h2 = (lane + 64) < C_;
        float v2 = h2 ? row[lane + 64] : -3.0e38f;
        float m = fmaxf(fmaxf(v0, v1), v2);
        #pragma unroll
        for (int off = 16; off; off >>= 1)
            m = fmaxf(m, __shfl_xor_sync(0xFFFFFFFFu, m, off));
        float e0 = expf(v0 - m);
        float e1 = expf(v1 - m);
        float e2 = h2 ? expf(v2 - m) : 0.f;
        float s = e0 + e1 + e2;
        #pragma unroll
        for (int off = 16; off; off >>= 1)
            s += __shfl_xor_sync(0xFFFFFFFFu, s, off);
        tile[lane][r]      = e0 / s;
        tile[lane + 32][r] = e1 / s;
        if (h2) tile[lane + 64][r] = e2 / s;
    }
    __syncthreads();
    // write classes 1..90 transposed: g_scores[b][c][n0+r]
    for (int k = threadIdx.x; k < CM_*32; k += 256) {
        int c = k >> 5;
        int r = k & 31;
        g_scores[((size_t)b*CM_ + c)*N_ + n0 + r] = tile[c+1][r];
    }
}

// ---------------- radix-select helper ----------------
// Finds bin b* such that above(b*) < target <= above(b*)+hist[b*],
// where above(b) = sum_{i>b} hist[i]. Assumes blockDim.x == 256.
__device__ void suffix_select(unsigned int* hist, int nb, unsigned int target,
                              int* out_bin, int* out_above, unsigned int* scanbuf)
{
    int t = threadIdx.x;
    int chunk = nb >> 8;
    unsigned int csum = 0;
    for (int k = 0; k < chunk; k++) csum += hist[t*chunk + k];
    if (t == 0) *out_bin = -1;
    scanbuf[t] = csum;
    __syncthreads();
    // inclusive suffix scan of 256 chunk sums
    for (int off = 1; off < 256; off <<= 1) {
        unsigned int v = scanbuf[t] + ((t + off) < 256 ? scanbuf[t + off] : 0u);
        __syncthreads();
        scanbuf[t] = v;
        __syncthreads();
    }
    unsigned int above = (t < 255) ? scanbuf[t+1] : 0u;
    if (above < target && above + csum >= target) {
        unsigned int run = above;
        for (int i = chunk - 1; i >= 0; i--) {
            int bin = t*chunk + i;
            unsigned int h = hist[bin];
            if (run < target && run + h >= target) {
                *out_bin = bin;
                *out_above = (int)run;
            }
            run += h;
        }
    }
    __syncthreads();
}

// descending bitonic sort of n u64 keys in smem (n power of 2)
__device__ void bitonic_desc(unsigned long long* a, int n)
{
    for (unsigned int k = 2; k <= (unsigned)n; k <<= 1) {
        for (unsigned int j = k >> 1; j > 0; j >>= 1) {
            for (unsigned int i = threadIdx.x; i < (unsigned)n; i += blockDim.x) {
                unsigned int ixj = i ^ j;
                if (ixj > i) {
                    unsigned long long x = a[i], y = a[ixj];
                    bool desc = ((i & k) == 0);
                    if (desc ? (x < y) : (x > y)) { a[i] = y; a[ixj] = x; }
                }
            }
            __syncthreads();
        }
    }
}

// ---------------- K2: per-(b,c) exact top-1000 ----------------
__global__ void topk_kernel()
{
    __shared__ unsigned int hist[4096];
    __shared__ unsigned int scanbuf[256];
    __shared__ unsigned long long cand[2048];
    __shared__ int s_bin, s_above, s_cnt;
    __shared__ int s_e, s_A1, s_m, s_A2;

    int blk = blockIdx.x;
    int t = threadIdx.x;
    const float* sc = g_scores + (size_t)blk * N_;

    // L1: exponent histogram (256 bins)
    for (int i = t; i < 256; i += 256) hist[i] = 0;
    __syncthreads();
    for (int i = t; i < N_; i += 256) {
        unsigned int bits = __float_as_uint(sc[i]);
        atomicAdd(&hist[bits >> 23], 1u);
    }
    __syncthreads();
    suffix_select(hist, 256, K_, &s_bin, &s_above, scanbuf);
    if (t == 0) { s_e = s_bin; s_A1 = s_above; }
    __syncthreads();
    int e = s_e, A1 = s_A1;

    // L2: mantissa bits [11..22] (4096 bins), values with exponent e
    for (int i = t; i < 4096; i += 256) hist[i] = 0;
    __syncthreads();
    for (int i = t; i < N_; i += 256) {
        unsigned int bits = __float_as_uint(sc[i]);
        if ((int)(bits >> 23) == e) atomicAdd(&hist[(bits >> 11) & 0xFFF], 1u);
    }
    __syncthreads();
    suffix_select(hist, 4096, (unsigned)(K_ - A1), &s_bin, &s_above, scanbuf);
    if (t == 0) { s_m = s_bin; s_A2 = s_above; }
    __syncthreads();
    int m = s_m, A2 = s_A2;

    // L3: mantissa bits [0..10] (2048 bins) -> exact bit threshold
    for (int i = t; i < 2048; i += 256) hist[i] = 0;
    __syncthreads();
    unsigned int hi = ((unsigned)e << 12) | (unsigned)m;
    for (int i = t; i < N_; i += 256) {
        unsigned int bits = __float_as_uint(sc[i]);
        if ((bits >> 11) == hi) atomicAdd(&hist[bits & 0x7FF], 1u);
    }
    __syncthreads();
    suffix_select(hist, 2048, (unsigned)(K_ - A1 - A2), &s_bin, &s_above, scanbuf);
    __syncthreads();
    unsigned int T = ((unsigned)e << 23) | ((unsigned)m << 11) | (unsigned)s_bin;

    // compact candidates with bits >= T
    if (t == 0) s_cnt = 0;
    __syncthreads();
    for (int i = t; i < N_; i += 256) {
        unsigned int bits = __float_as_uint(sc[i]);
        if (bits >= T) {
            int p = atomicAdd(&s_cnt, 1);
            if (p < 2048)
                cand[p] = ((unsigned long long)bits << 32) |
                          (unsigned long long)(0xFFFFFFFFu - (unsigned)i);
        }
    }
    __syncthreads();
    int C = s_cnt < 2048 ? s_cnt : 2048;
    for (int i = t; i < 2048; i += 256)
        if (i >= C) cand[i] = 0ull;
    __syncthreads();

    bitonic_desc(cand, 2048);

    for (int i = t; i < K_; i += 256) {
        unsigned long long key = cand[i];
        g_topk_score[(size_t)blk*K_ + i] = __uint_as_float((unsigned int)(key >> 32));
        g_topk_idx[(size_t)blk*K_ + i]   = (int)(0xFFFFFFFFu - (unsigned int)key);
    }
}

// ---------------- K3: decode + greedy NMS per (b,c) ----------------
__global__ void nms_kernel(const float* __restrict__ box_outputs,
                           const float* __restrict__ anchors,
                           const float* __restrict__ image_info)
{
    __shared__ float y0[K_], x0[K_], y1[K_], x1[K_], ar[K_];
    __shared__ unsigned char sup[K_];

    int blk = blockIdx.x;
    int b   = blk / CM_;
    int cm  = blk % CM_;
    float h = image_info[b*4 + 0];
    float w = image_info[b*4 + 1];

    for (int i = threadIdx.x; i < K_; i += blockDim.x) {
        int idx = g_topk_idx[(size_t)blk*K_ + i];
        float s = g_topk_score[(size_t)blk*K_ + i];
        const float* anc = anchors + ((size_t)b*N_ + idx)*4;
        float a0 = anc[0], a1 = anc[1], a2 = anc[2], a3 = anc[3];
        const float* e4 = box_outputs + ((size_t)b*N_ + idx)*(C_*4) + (cm+1)*4;
        float ty = e4[0] / 10.f;
        float tx = e4[1] / 10.f;
        float th = fminf(e4[2] / 5.f, BBOX_CLIP);
        float tw = fminf(e4[3] / 5.f, BBOX_CLIP);
        float ah = a2 - a0, aw = a3 - a1;
        float acy = a0 + 0.5f*ah, acx = a1 + 0.5f*aw;
        float cy = ty*ah + acy, cx = tx*aw + acx;
        float hh = expf(th)*ah, ww = expf(tw)*aw;
        float b0 = cy - 0.5f*hh, b1 = cx - 0.5f*ww;
        float b2 = cy + 0.5f*hh, b3 = cx + 0.5f*ww;
        b0 = fminf(fmaxf(b0, 0.f), h);
        b1 = fminf(fmaxf(b1, 0.f), w);
        b2 = fminf(fmaxf(b2, 0.f), h);
        b3 = fminf(fmaxf(b3, 0.f), w);
        b0 /= h; b1 /= w; b2 /= h; b3 /= w;
        y0[i] = b0; x0[i] = b1; y1[i] = b2; x1[i] = b3;
        ar[i] = fmaxf(b2 - b0, 0.f) * fmaxf(b3 - b1, 0.f);
        sup[i] = (s > 0.f) ? 0 : 1;   // non-passing boxes never kept / never suppress
        float* nb = g_nboxes + ((size_t)blk*K_ + i)*4;
        nb[0] = b0; nb[1] = b1; nb[2] = b2; nb[3] = b3;
    }
    __syncthreads();

    for (int i = 0; i < K_; i++) {
        if (!sup[i]) {
            float iy0 = y0[i], ix0 = x0[i], iy1 = y1[i], ix1 = x1[i], ia = ar[i];
            for (int j = i + 1 + threadIdx.x; j < K_; j += blockDim.x) {
                if (sup[j]) continue;
                float ih = fmaxf(fminf(iy1, y1[j]) - fmaxf(iy0, y0[j]), 0.f);
                float iw = fmaxf(fminf(ix1, x1[j]) - fmaxf(ix0, x0[j]), 0.f);
                float inter = ih * iw;
                float iou = inter / (((ia + ar[j]) - inter) + 1e-8f);
                if (iou > IOU_THR) sup[j] = 1;
            }
        }
        __syncthreads();
    }

    for (int i = threadIdx.x; i < K_; i += blockDim.x) {
        float s = g_topk_score[(size_t)blk*K_ + i];
        g_kept[(size_t)blk*K_ + i] = (!sup[i] && s > 0.f) ? s : -1.0f;
    }
}

// ---------------- K4: per-image global top-100 + output ----------------
__global__ void final_kernel(const float* __restrict__ image_info,
                             float* __restrict__ out)
{
    __shared__ unsigned int hist[4096];
    __shared__ unsigned int scanbuf[256];
    __shared__ unsigned long long cand[256];
    __shared__ int s_bin, s_above, s_cnt, s_valid;
    __shared__ int s_e, s_A1, s_m, s_A2;
    __shared__ unsigned int s_T;

    int b = blockIdx.x;
    int t = threadIdx.x;
    const float* ks = g_kept + (size_t)b * CM_ * K_;
    const int M = CM_ * K_;   // 90000

    // L1 (positive values only)
    for (int i = t; i < 256; i += 256) hist[i] = 0;
    __syncthreads();
    for (int i = t; i < M; i += 256) {
        float v = ks[i];
        if (v > 0.f) atomicAdd(&hist[__float_as_uint(v) >> 23], 1u);
    }
    __syncthreads();
    suffix_select(hist, 256, MAXT_, &s_bin, &s_above, scanbuf);
    if (t == 0) { s_e = s_bin; s_A1 = s_above; }
    __syncthreads();

    if (s_e < 0) {
        if (t == 0) s_T = 1u;   // fewer than 100 positives: take them all
        __syncthreads();
    } else {
        int e = s_e, A1 = s_A1;
        for (int i = t; i < 4096; i += 256) hist[i] = 0;
        __syncthreads();
        for (int i = t; i < M; i += 256) {
            float v = ks[i];
            if (v > 0.f) {
                unsigned int bits = __float_as_uint(v);
                if ((int)(bits >> 23) == e) atomicAdd(&hist[(bits >> 11) & 0xFFF], 1u);
            }
        }
        __syncthreads();
        suffix_select(hist, 4096, (unsigned)(MAXT_ - A1), &s_bin, &s_above, scanbuf);
        if (t == 0) { s_m = s_bin; s_A2 = s_above; }
        __syncthreads();
        int m = s_m, A2 = s_A2;
        for (int i = t; i < 2048; i += 256) hist[i] = 0;
        __syncthreads();
        unsigned int hi = ((unsigned)e << 12) | (unsigned)m;
        for (int i = t; i < M; i += 256) {
            float v = ks[i];
            if (v > 0.f) {
                unsigned int bits = __float_as_uint(v);
                if ((bits >> 11) == hi) atomicAdd(&hist[bits & 0x7FF], 1u);
            }
        }
        __syncthreads();
        suffix_select(hist, 2048, (unsigned)(MAXT_ - A1 - A2), &s_bin, &s_above, scanbuf);
        if (t == 0) s_T = ((unsigned)e << 23) | ((unsigned)m << 11) | (unsigned)s_bin;
        __syncthreads();
    }
    unsigned int T = s_T;

    if (t == 0) { s_cnt = 0; s_valid = 0; }
    __syncthreads();
    for (int i = t; i < M; i += 256) {
        float v = ks[i];
        if (v > 0.f) {
            unsigned int bits = __float_as_uint(v);
            if (bits >= T) {
                int p = atomicAdd(&s_cnt, 1);
                if (p < 256)
                    cand[p] = ((unsigned long long)bits << 32) |
                              (unsigned long long)(0xFFFFFFFFu - (unsigned)i);
            }
        }
    }
    __syncthreads();
    int C = s_cnt < 256 ? s_cnt : 256;
    for (int i = t; i < 256; i += 256)
        if (i >= C) cand[i] = 0ull;
    __syncthreads();

    bitonic_desc(cand, 256);

    float h = image_info[b*4 + 0];
    float w = image_info[b*4 + 1];
    for (int i = t; i < MAXT_; i += 256) {
        unsigned long long key = cand[i];
        float s = __uint_as_float((unsigned int)(key >> 32));
        bool valid = (s > 0.f);
        float b0 = 0.f, b1 = 0.f, b2 = 0.f, b3 = 0.f, cl = 0.f, so = 0.f;
        if (valid) {
            unsigned int flat = 0xFFFFFFFFu - (unsigned int)key;
            int c = flat / K_;
            int k = flat % K_;
            const float* nb = g_nboxes + ((size_t)(b*CM_ + c)*K_ + k)*4;
            b0 = nb[0]*h; b1 = nb[1]*w; b2 = nb[2]*h; b3 = nb[3]*w;
            cl = (float)(c + 1);
            so = s;
            atomicAdd(&s_valid, 1);
        }
        float* ob = out + B_ + (size_t)(b*MAXT_ + i)*4;
        ob[0] = b0; ob[1] = b1; ob[2] = b2; ob[3] = b3;
        out[B_ + B_*MAXT_*4 + b*MAXT_ + i] = cl;
        out[B_ + B_*MAXT_*4 + B_*MAXT_ + b*MAXT_ + i] = so;
    }
    __syncthreads();
    if (t == 0) out[b] = (float)s_valid;
}

// ---------------- launch ----------------
extern "C" void kernel_launch(void* const* d_in, const int* in_sizes, int n_in,
                              void* d_out, int out_size)
{
    const float* cls  = (const float*)d_in[0];
    const float* box  = (const float*)d_in[1];
    const float* anc  = (const float*)d_in[2];
    const float* info = (const float*)d_in[3];
    float* out = (float*)d_out;

    softmax_kernel<<<B_*(N_/32), 256>>>(cls);
    topk_kernel<<<NPROB, 256>>>();
    nms_kernel<<<NPROB, 512>>>(box, anc, info);
    final_kernel<<<B_, 256>>>(info, out);
}

// round 2
// speedup vs baseline: 5.6300x; 5.6300x over previous
#include <cuda_runtime.h>
#include <math.h>

#define B_    8
#define N_    8192
#define C_    91
#define CM_   90
#define K_    1000
#define T_    128
#define MAXT_ 100
#define NPROB (B_*CM_)

#define BBOX_CLIP 4.135166556742356f
#define IOU_THR   0.3f

// ---------------- scratch (device globals: allocation-free) ----------------
__device__ float g_scores[B_*CM_*N_];        // [b][cm][n]  transposed scores
__device__ float g_nboxes[NPROB*K_*4];       // decoded normalized boxes (valid prefix g_cnt)
__device__ float g_kept[NPROB*K_];           // kept score or -1 (valid prefix g_cnt)
__device__ int   g_cnt[NPROB];               // valid prefix length per class
__device__ unsigned int g_Lbits[B_];         // per-image bit threshold (lower bound on 100th kept)

// ---------------- K1: softmax + transpose ----------------
__global__ void softmax_kernel(const float* __restrict__ cls)
{
    __shared__ float tile[C_][33];
    int cta  = blockIdx.x;
    int b    = cta / (N_/32);
    int n0   = (cta % (N_/32)) * 32;
    int warp = threadIdx.x >> 5;
    int lane = threadIdx.x & 31;

    for (int rr = 0; rr < 4; rr++) {
        int r = warp*4 + rr;
        const float* row = cls + ((size_t)b*N_ + n0 + r) * C_;
        float v0 = row[lane];
        float v1 = row[lane + 32];
        bool  h2 = (lane + 64) < C_;
        float v2 = h2 ? row[lane + 64] : -3.0e38f;
        float m = fmaxf(fmaxf(v0, v1), v2);
        #pragma unroll
        for (int off = 16; off; off >>= 1)
            m = fmaxf(m, __shfl_xor_sync(0xFFFFFFFFu, m, off));
        float e0 = expf(v0 - m);
        float e1 = expf(v1 - m);
        float e2 = h2 ? expf(v2 - m) : 0.f;
        float s = e0 + e1 + e2;
        #pragma unroll
        for (int off = 16; off; off >>= 1)
            s += __shfl_xor_sync(0xFFFFFFFFu, s, off);
        tile[lane][r]      = e0 / s;
        tile[lane + 32][r] = e1 / s;
        if (h2) tile[lane + 64][r] = e2 / s;
    }
    __syncthreads();
    for (int k = threadIdx.x; k < CM_*32; k += 256) {
        int c = k >> 5;
        int r = k & 31;
        g_scores[((size_t)b*CM_ + c)*N_ + n0 + r] = tile[c+1][r];
    }
}

// ---------------- radix-select helper (blockDim.x == 256) ----------------
__device__ void suffix_select(unsigned int* hist, int nb, unsigned int target,
                              int* out_bin, int* out_above, unsigned int* scanbuf)
{
    int t = threadIdx.x;
    int chunk = nb >> 8;
    unsigned int csum = 0;
    for (int k = 0; k < chunk; k++) csum += hist[t*chunk + k];
    if (t == 0) *out_bin = -1;
    scanbuf[t] = csum;
    __syncthreads();
    for (int off = 1; off < 256; off <<= 1) {
        unsigned int v = scanbuf[t] + ((t + off) < 256 ? scanbuf[t + off] : 0u);
        __syncthreads();
        scanbuf[t] = v;
        __syncthreads();
    }
    unsigned int above = (t < 255) ? scanbuf[t+1] : 0u;
    if (above < target && above + csum >= target) {
        unsigned int run = above;
        for (int i = chunk - 1; i >= 0; i--) {
            int bin = t*chunk + i;
            unsigned int h = hist[bin];
            if (run < target && run + h >= target) {
                *out_bin = bin;
                *out_above = (int)run;
            }
            run += h;
        }
    }
    __syncthreads();
}

// descending bitonic sort of n u64 keys in smem (n power of 2)
__device__ void bitonic_desc(unsigned long long* a, int n)
{
    for (unsigned int k = 2; k <= (unsigned)n; k <<= 1) {
        for (unsigned int j = k >> 1; j > 0; j >>= 1) {
            for (unsigned int i = threadIdx.x; i < (unsigned)n; i += blockDim.x) {
                unsigned int ixj = i ^ j;
                if (ixj > i) {
                    unsigned long long x = a[i], y = a[ixj];
                    bool desc = ((i & k) == 0);
                    if (desc ? (x < y) : (x > y)) { a[i] = y; a[ixj] = x; }
                }
            }
            __syncthreads();
        }
    }
}

// ---------------- box decode (identical expression to R1 kernel) ----------------
__device__ __forceinline__ void decode_one(
    const float* __restrict__ box_outputs, const float* __restrict__ anchors,
    int b, int cm, int idx, float h, float w,
    float& b0, float& b1, float& b2, float& b3)
{
    const float* anc = anchors + ((size_t)b*N_ + idx)*4;
    float a0 = anc[0], a1 = anc[1], a2 = anc[2], a3 = anc[3];
    const float* e4 = box_outputs + ((size_t)b*N_ + idx)*(C_*4) + (cm+1)*4;
    float ty = e4[0] / 10.f;
    float tx = e4[1] / 10.f;
    float th = fminf(e4[2] / 5.f, BBOX_CLIP);
    float tw = fminf(e4[3] / 5.f, BBOX_CLIP);
    float ah = a2 - a0, aw = a3 - a1;
    float acy = a0 + 0.5f*ah, acx = a1 + 0.5f*aw;
    float cy = ty*ah + acy, cx = tx*aw + acx;
    float hh = expf(th)*ah, ww = expf(tw)*aw;
    b0 = cy - 0.5f*hh; b1 = cx - 0.5f*ww;
    b2 = cy + 0.5f*hh; b3 = cx + 0.5f*ww;
    b0 = fminf(fmaxf(b0, 0.f), h); b0 /= h;
    b1 = fminf(fmaxf(b1, 0.f), w); b1 /= w;
    b2 = fminf(fmaxf(b2, 0.f), h); b2 /= h;
    b3 = fminf(fmaxf(b3, 0.f), w); b3 /= w;
}

// ---------------- K2: fused top-128 select + decode + truncated NMS ----------------
__global__ void topk_nms_kernel(const float* __restrict__ box_outputs,
                                const float* __restrict__ anchors,
                                const float* __restrict__ image_info)
{
    __shared__ unsigned int hist[4096];
    __shared__ unsigned int scanbuf[256];
    __shared__ unsigned long long cand[256];
    __shared__ float y0[T_], x0[T_], y1[T_], x1[T_], ar[T_];
    __shared__ unsigned char sup[T_];
    __shared__ int s_bin, s_above, s_cnt;
    __shared__ int s_e, s_A1, s_m, s_A2;

    int blk = blockIdx.x;
    int t = threadIdx.x;
    const float* sc = g_scores + (size_t)blk * N_;

    // L1: exponent histogram
    for (int i = t; i < 256; i += 256) hist[i] = 0;
    __syncthreads();
    for (int i = t; i < N_; i += 256) {
        unsigned int bits = __float_as_uint(sc[i]);
        atomicAdd(&hist[bits >> 23], 1u);
    }
    __syncthreads();
    suffix_select(hist, 256, T_, &s_bin, &s_above, scanbuf);
    if (t == 0) { s_e = s_bin; s_A1 = s_above; }
    __syncthreads();
    int e = s_e, A1 = s_A1;

    // L2: mantissa [11..22]
    for (int i = t; i < 4096; i += 256) hist[i] = 0;
    __syncthreads();
    for (int i = t; i < N_; i += 256) {
        unsigned int bits = __float_as_uint(sc[i]);
        if ((int)(bits >> 23) == e) atomicAdd(&hist[(bits >> 11) & 0xFFF], 1u);
    }
    __syncthreads();
    suffix_select(hist, 4096, (unsigned)(T_ - A1), &s_bin, &s_above, scanbuf);
    if (t == 0) { s_m = s_bin; s_A2 = s_above; }
    __syncthreads();
    int m = s_m, A2 = s_A2;

    // L3: mantissa [0..10] -> exact threshold
    for (int i = t; i < 2048; i += 256) hist[i] = 0;
    __syncthreads();
    unsigned int hi = ((unsigned)e << 12) | (unsigned)m;
    for (int i = t; i < N_; i += 256) {
        unsigned int bits = __float_as_uint(sc[i]);
        if ((bits >> 11) == hi) atomicAdd(&hist[bits & 0x7FF], 1u);
    }
    __syncthreads();
    suffix_select(hist, 2048, (unsigned)(T_ - A1 - A2), &s_bin, &s_above, scanbuf);
    __syncthreads();
    unsigned int T = ((unsigned)e << 23) | ((unsigned)m << 11) | (unsigned)s_bin;

    // compact candidates bits >= T (cap 256)
    if (t == 0) s_cnt = 0;
    __syncthreads();
    for (int i = t; i < N_; i += 256) {
        unsigned int bits = __float_as_uint(sc[i]);
        if (bits >= T) {
            int p = atomicAdd(&s_cnt, 1);
            if (p < 256)
                cand[p] = ((unsigned long long)bits << 32) |
                          (unsigned long long)(0xFFFFFFFFu - (unsigned)i);
        }
    }
    __syncthreads();
    if (s_cnt > 256) {           // massive ties: defer whole class to fixup
        if (t == 0) g_cnt[blk] = 0;
        return;
    }
    int Csel = s_cnt;
    for (int i = t; i < 256; i += 256)
        if (i >= Csel) cand[i] = 0ull;
    __syncthreads();

    bitonic_desc(cand, 256);

    int nv = Csel < T_ ? Csel : T_;
    int b  = blk / CM_;
    int cm = blk % CM_;
    float h = image_info[b*4 + 0];
    float w = image_info[b*4 + 1];

    if (t < nv) {
        unsigned long long key = cand[t];
        float s = __uint_as_float((unsigned int)(key >> 32));
        int idx = (int)(0xFFFFFFFFu - (unsigned int)key);
        float b0, b1, b2, b3;
        decode_one(box_outputs, anchors, b, cm, idx, h, w, b0, b1, b2, b3);
        y0[t] = b0; x0[t] = b1; y1[t] = b2; x1[t] = b3;
        ar[t] = fmaxf(b2 - b0, 0.f) * fmaxf(b3 - b1, 0.f);
        sup[t] = (s > 0.f) ? 0 : 1;
        float* nb = g_nboxes + ((size_t)blk*K_ + t)*4;
        nb[0] = b0; nb[1] = b1; nb[2] = b2; nb[3] = b3;
    }
    __syncthreads();

    // greedy NMS over the 128-prefix (exact for these ranks)
    for (int i = 0; i < nv; i++) {
        if (!sup[i]) {
            if (t > i && t < nv && !sup[t]) {
                float ih = fmaxf(fminf(y1[i], y1[t]) - fmaxf(y0[i], y0[t]), 0.f);
                float iw = fmaxf(fminf(x1[i], x1[t]) - fmaxf(x0[i], x0[t]), 0.f);
                float inter = ih * iw;
                float iou = inter / (((ar[i] + ar[t]) - inter) + 1e-8f);
                if (iou > IOU_THR) sup[t] = 1;
            }
        }
        __syncthreads();
    }

    if (t < nv) {
        float s = __uint_as_float((unsigned int)(cand[t] >> 32));
        g_kept[(size_t)blk*K_ + t] = (!sup[t]) ? s : -1.0f;
    }
    if (t == 0) g_cnt[blk] = nv;
}

// ---------------- K3: per-image L = 100th-highest phase-1 kept score ----------------
__global__ void computeL_kernel()
{
    __shared__ unsigned int hist[4096];
    __shared__ unsigned int scanbuf[256];
    __shared__ int cnts[CM_];
    __shared__ int s_bin, s_above, s_e, s_A1, s_m, s_A2;

    int b = blockIdx.x;
    int t = threadIdx.x;
    const float* ks = g_kept + (size_t)b * CM_ * K_;

    for (int c = t; c < CM_; c += 256) cnts[c] = g_cnt[b*CM_ + c];

    // L1
    for (int i = t; i < 256; i += 256) hist[i] = 0;
    __syncthreads();
    for (int k = t; k < CM_*T_; k += 256) {
        int c = k / T_, i = k % T_;
        if (i < cnts[c]) {
            float v = ks[(size_t)c*K_ + i];
            if (v > 0.f) atomicAdd(&hist[__float_as_uint(v) >> 23], 1u);
        }
    }
    __syncthreads();
    suffix_select(hist, 256, MAXT_, &s_bin, &s_above, scanbuf);
    if (t == 0) { s_e = s_bin; s_A1 = s_above; }
    __syncthreads();

    if (s_e < 0) {                 // fewer than 100 kept in prefixes
        if (t == 0) g_Lbits[b] = 1u;
        return;
    }
    int e = s_e, A1 = s_A1;

    // L2
    for (int i = t; i < 4096; i += 256) hist[i] = 0;
    __syncthreads();
    for (int k = t; k < CM_*T_; k += 256) {
        int c = k / T_, i = k % T_;
        if (i < cnts[c]) {
            float v = ks[(size_t)c*K_ + i];
            if (v > 0.f) {
                unsigned int bits = __float_as_uint(v);
                if ((int)(bits >> 23) == e) atomicAdd(&hist[(bits >> 11) & 0xFFF], 1u);
            }
        }
    }
    __syncthreads();
    suffix_select(hist, 4096, (unsigned)(MAXT_ - A1), &s_bin, &s_above, scanbuf);
    if (t == 0) { s_m = s_bin; s_A2 = s_above; }
    __syncthreads();
    int m = s_m, A2 = s_A2;

    // L3
    for (int i = t; i < 2048; i += 256) hist[i] = 0;
    __syncthreads();
    unsigned int hi = ((unsigned)e << 12) | (unsigned)m;
    for (int k = t; k < CM_*T_; k += 256) {
        int c = k / T_, i = k % T_;
        if (i < cnts[c]) {
            float v = ks[(size_t)c*K_ + i];
            if (v > 0.f) {
                unsigned int bits = __float_as_uint(v);
                if ((bits >> 11) == hi) atomicAdd(&hist[bits & 0x7FF], 1u);
            }
        }
    }
    __syncthreads();
    suffix_select(hist, 2048, (unsigned)(MAXT_ - A1 - A2), &s_bin, &s_above, scanbuf);
    if (t == 0)
        g_Lbits[b] = ((unsigned)e << 23) | ((unsigned)m << 11) | (unsigned)s_bin;
}

// ---------------- K4: fixup — full NMS only where prefix was insufficient ----------------
__global__ void fixup_kernel(const float* __restrict__ box_outputs,
                             const float* __restrict__ anchors,
                             const float* __restrict__ image_info)
{
    __shared__ unsigned long long cand[2048];          // aliases hist
    __shared__ unsigned int scanbuf[256];
    __shared__ float y0[K_], x0[K_], y1[K_], x1[K_], ar[K_];
    __shared__ unsigned char sup[K_];
    __shared__ int s_bin, s_above, s_cnt;
    __shared__ int s_e, s_A1, s_m, s_A2;
    unsigned int* hist = (unsigned int*)cand;          // used strictly before cand

    int blk = blockIdx.x;
    int t = threadIdx.x;
    int b = blk / CM_;
    int cm = blk % CM_;
    unsigned int L = g_Lbits[b];
    const float* sc = g_scores + (size_t)blk * N_;

    // count scores with bits >= L
    int cnt = 0;
    for (int i = t; i < N_; i += 256)
        cnt += (__float_as_uint(sc[i]) >= L) ? 1 : 0;
    scanbuf[t] = (unsigned)cnt;
    __syncthreads();
    for (int off = 128; off > 0; off >>= 1) {
        if (t < off) scanbuf[t] += scanbuf[t + off];
        __syncthreads();
    }
    int count = (int)scanbuf[0];
    __syncthreads();

    if (count <= g_cnt[blk]) return;     // prefix already covers every score >= L

    // determine selection threshold
    unsigned int T;
    if (count <= K_) {
        T = L;
    } else {
        // exact top-1000 threshold via 3-level radix
        for (int i = t; i < 256; i += 256) hist[i] = 0;
        __syncthreads();
        for (int i = t; i < N_; i += 256)
            atomicAdd(&hist[__float_as_uint(sc[i]) >> 23], 1u);
        __syncthreads();
        suffix_select(hist, 256, K_, &s_bin, &s_above, scanbuf);
        if (t == 0) { s_e = s_bin; s_A1 = s_above; }
        __syncthreads();
        int e = s_e, A1 = s_A1;

        for (int i = t; i < 4096; i += 256) hist[i] = 0;
        __syncthreads();
        for (int i = t; i < N_; i += 256) {
            unsigned int bits = __float_as_uint(sc[i]);
            if ((int)(bits >> 23) == e) atomicAdd(&hist[(bits >> 11) & 0xFFF], 1u);
        }
        __syncthreads();
        suffix_select(hist, 4096, (unsigned)(K_ - A1), &s_bin, &s_above, scanbuf);
        if (t == 0) { s_m = s_bin; s_A2 = s_above; }
        __syncthreads();
        int m = s_m, A2 = s_A2;

        for (int i = t; i < 2048; i += 256) hist[i] = 0;
        __syncthreads();
        unsigned int hi = ((unsigned)e << 12) | (unsigned)m;
        for (int i = t; i < N_; i += 256) {
            unsigned int bits = __float_as_uint(sc[i]);
            if ((bits >> 11) == hi) atomicAdd(&hist[bits & 0x7FF], 1u);
        }
        __syncthreads();
        suffix_select(hist, 2048, (unsigned)(K_ - A1 - A2), &s_bin, &s_above, scanbuf);
        __syncthreads();
        T = ((unsigned)e << 23) | ((unsigned)m << 11) | (unsigned)s_bin;
    }

    // compact
    if (t == 0) s_cnt = 0;
    __syncthreads();
    for (int i = t; i < N_; i += 256) {
        unsigned int bits = __float_as_uint(sc[i]);
        if (bits >= T) {
            int p = atomicAdd(&s_cnt, 1);
            if (p < 2048)
                cand[p] = ((unsigned long long)bits << 32) |
                          (unsigned long long)(0xFFFFFFFFu - (unsigned)i);
        }
    }
    __syncthreads();
    int Csel = s_cnt < 2048 ? s_cnt : 2048;
    for (int i = t; i < 2048; i += 256)
        if (i >= Csel) cand[i] = 0ull;
    __syncthreads();

    bitonic_desc(cand, 2048);

    int M = count < K_ ? count : K_;
    if (M > Csel) M = Csel;
    float h = image_info[b*4 + 0];
    float w = image_info[b*4 + 1];

    for (int i = t; i < M; i += 256) {
        unsigned long long key = cand[i];
        float s = __uint_as_float((unsigned int)(key >> 32));
        int idx = (int)(0xFFFFFFFFu - (unsigned int)key);
        float b0, b1, b2, b3;
        decode_one(box_outputs, anchors, b, cm, idx, h, w, b0, b1, b2, b3);
        y0[i] = b0; x0[i] = b1; y1[i] = b2; x1[i] = b3;
        ar[i] = fmaxf(b2 - b0, 0.f) * fmaxf(b3 - b1, 0.f);
        sup[i] = (s > 0.f) ? 0 : 1;
        float* nb = g_nboxes + ((size_t)blk*K_ + i)*4;
        nb[0] = b0; nb[1] = b1; nb[2] = b2; nb[3] = b3;
    }
    __syncthreads();

    for (int i = 0; i < M; i++) {
        if (!sup[i]) {
            float iy0 = y0[i], ix0 = x0[i], iy1 = y1[i], ix1 = x1[i], ia = ar[i];
            for (int j = i + 1 + t; j < M; j += 256) {
                if (sup[j]) continue;
                float ih = fmaxf(fminf(iy1, y1[j]) - fmaxf(iy0, y0[j]), 0.f);
                float iw = fmaxf(fminf(ix1, x1[j]) - fmaxf(ix0, x0[j]), 0.f);
                float inter = ih * iw;
                float iou = inter / (((ia + ar[j]) - inter) + 1e-8f);
                if (iou > IOU_THR) sup[j] = 1;
            }
        }
        __syncthreads();
    }

    for (int i = t; i < M; i += 256) {
        float s = __uint_as_float((unsigned int)(cand[i] >> 32));
        g_kept[(size_t)blk*K_ + i] = (!sup[i]) ? s : -1.0f;
    }
    if (t == 0) g_cnt[blk] = M;
}

// ---------------- K5: per-image global top-100 + output ----------------
__global__ void final_kernel(const float* __restrict__ image_info,
                             float* __restrict__ out)
{
    __shared__ unsigned int hist[4096];
    __shared__ unsigned int scanbuf[256];
    __shared__ unsigned long long cand[256];
    __shared__ int cnts[CM_];
    __shared__ int s_bin, s_above, s_cnt, s_valid;
    __shared__ int s_e, s_A1, s_m, s_A2;
    __shared__ unsigned int s_T;

    int b = blockIdx.x;
    int t = threadIdx.x;
    const float* ks = g_kept + (size_t)b * CM_ * K_;

    for (int c = t; c < CM_; c += 256) cnts[c] = g_cnt[b*CM_ + c];
    __syncthreads();

    // L1
    for (int i = t; i < 256; i += 256) hist[i] = 0;
    __syncthreads();
    for (int c = 0; c < CM_; c++) {
        int cn = cnts[c];
        for (int i = t; i < cn; i += 256) {
            float v = ks[(size_t)c*K_ + i];
            if (v > 0.f) atomicAdd(&hist[__float_as_uint(v) >> 23], 1u);
        }
    }
    __syncthreads();
    suffix_select(hist, 256, MAXT_, &s_bin, &s_above, scanbuf);
    if (t == 0) { s_e = s_bin; s_A1 = s_above; }
    __syncthreads();

    if (s_e < 0) {
        if (t == 0) s_T = 1u;
        __syncthreads();
    } else {
        int e = s_e, A1 = s_A1;
        for (int i = t; i < 4096; i += 256) hist[i] = 0;
        __syncthreads();
        for (int c = 0; c < CM_; c++) {
            int cn = cnts[c];
            for (int i = t; i < cn; i += 256) {
                float v = ks[(size_t)c*K_ + i];
                if (v > 0.f) {
                    unsigned int bits = __float_as_uint(v);
                    if ((int)(bits >> 23) == e) atomicAdd(&hist[(bits >> 11) & 0xFFF], 1u);
                }
            }
        }
        __syncthreads();
        suffix_select(hist, 4096, (unsigned)(MAXT_ - A1), &s_bin, &s_above, scanbuf);
        if (t == 0) { s_m = s_bin; s_A2 = s_above; }
        __syncthreads();
        int m = s_m, A2 = s_A2;

        for (int i = t; i < 2048; i += 256) hist[i] = 0;
        __syncthreads();
        unsigned int hi = ((unsigned)e << 12) | (unsigned)m;
        for (int c = 0; c < CM_; c++) {
            int cn = cnts[c];
            for (int i = t; i < cn; i += 256) {
                float v = ks[(size_t)c*K_ + i];
                if (v > 0.f) {
                    unsigned int bits = __float_as_uint(v);
                    if ((bits >> 11) == hi) atomicAdd(&hist[bits & 0x7FF], 1u);
                }
            }
        }
        __syncthreads();
        suffix_select(hist, 2048, (unsigned)(MAXT_ - A1 - A2), &s_bin, &s_above, scanbuf);
        if (t == 0) s_T = ((unsigned)e << 23) | ((unsigned)m << 11) | (unsigned)s_bin;
        __syncthreads();
    }
    unsigned int T = s_T;

    if (t == 0) { s_cnt = 0; s_valid = 0; }
    __syncthreads();
    for (int c = 0; c < CM_; c++) {
        int cn = cnts[c];
        for (int i = t; i < cn; i += 256) {
            float v = ks[(size_t)c*K_ + i];
            if (v > 0.f) {
                unsigned int bits = __float_as_uint(v);
                if (bits >= T) {
                    int p = atomicAdd(&s_cnt, 1);
                    if (p < 256) {
                        unsigned int flat = (unsigned)(c*K_ + i);
                        cand[p] = ((unsigned long long)bits << 32) |
                                  (unsigned long long)(0xFFFFFFFFu - flat);
                    }
                }
            }
        }
    }
    __syncthreads();
    int Csel = s_cnt < 256 ? s_cnt : 256;
    for (int i = t; i < 256; i += 256)
        if (i >= Csel) cand[i] = 0ull;
    __syncthreads();

    bitonic_desc(cand, 256);

    float h = image_info[b*4 + 0];
    float w = image_info[b*4 + 1];
    for (int i = t; i < MAXT_; i += 256) {
        unsigned long long key = cand[i];
        float s = __uint_as_float((unsigned int)(key >> 32));
        bool valid = (s > 0.f);
        float b0 = 0.f, b1 = 0.f, b2 = 0.f, b3 = 0.f, cl = 0.f, so = 0.f;
        if (valid) {
            unsigned int flat = 0xFFFFFFFFu - (unsigned int)key;
            int c = flat / K_;
            int k = flat % K_;
            const float* nb = g_nboxes + ((size_t)(b*CM_ + c)*K_ + k)*4;
            b0 = nb[0]*h; b1 = nb[1]*w; b2 = nb[2]*h; b3 = nb[3]*w;
            cl = (float)(c + 1);
            so = s;
            atomicAdd(&s_valid, 1);
        }
        float* ob = out + B_ + (size_t)(b*MAXT_ + i)*4;
        ob[0] = b0; ob[1] = b1; ob[2] = b2; ob[3] = b3;
        out[B_ + B_*MAXT_*4 + b*MAXT_ + i] = cl;
        out[B_ + B_*MAXT_*4 + B_*MAXT_ + b*MAXT_ + i] = so;
    }
    __syncthreads();
    if (t == 0) out[b] = (float)s_valid;
}

// ---------------- launch ----------------
extern "C" void kernel_launch(void* const* d_in, const int* in_sizes, int n_in,
                              void* d_out, int out_size)
{
    const float* cls  = (const float*)d_in[0];
    const float* box  = (const float*)d_in[1];
    const float* anc  = (const float*)d_in[2];
    const float* info = (const float*)d_in[3];
    float* out = (float*)d_out;

    softmax_kernel<<<B_*(N_/32), 256>>>(cls);
    topk_nms_kernel<<<NPROB, 256>>>(box, anc, info);
    computeL_kernel<<<B_, 256>>>();
    fixup_kernel<<<NPROB, 256>>>(box, anc, info);
    final_kernel<<<B_, 256>>>(info, out);
}